// round 14
// baseline (speedup 1.0000x reference)
#include <cuda_runtime.h>
#include <math.h>
#include <stdint.h>

typedef unsigned long long ull;

#define Bb     16
#define Vv     32000
#define Hd     512
#define BK     128          // B*K rows
#define Tt     32
#define NT     250          // logits CTAs / partial tiles of 128 cols
#define G3H    1536
#define SOS_T  1
#define EOS_T  2

// ------------------------------------------------------------------
// Persistent device state (no cudaMalloc allowed)
// ------------------------------------------------------------------
__device__ float g_h[2][BK * Hd];       // hidden ping-pong
__device__ float g_hT[Hd * BK];         // transposed h_new for logits A-tiles
__device__ float g_gi[BK * G3H];
__device__ float g_gh[BK * G3H];
__device__ float g_pmax[NT * BK];       // per-128-col-tile row max  [tile][row]
__device__ float g_psum[NT * BK];       // per-128-col-tile row sumexp [tile][row]
__device__ float g_lse[BK];
__device__ int   g_tokens[BK];
__device__ int   g_perm[BK];
__device__ float g_scores[BK];
__device__ ull   g_ckeyN[(size_t)BK * NT * 8];  // per-(row,128-tile) top-8 keys
__device__ int   g_ctrL;                // logits tile-arrival counter (monotonic)
__device__ int   g_lseCtr;              // lse slice counter (monotonic)

// ------------------------------------------------------------------
// Helpers
// ------------------------------------------------------------------
__device__ __forceinline__ ull pack2(float x, float y) {
    ull r; asm("mov.b64 %0, {%1, %2};" : "=l"(r) : "f"(x), "f"(y)); return r;
}
__device__ __forceinline__ void ffma2(ull& d, ull a, ull b) {
    asm("fma.rn.f32x2 %0, %1, %2, %0;" : "+l"(d) : "l"(a), "l"(b));
}
__device__ __forceinline__ float2 unpack2(ull v) {
    float2 r; asm("mov.b64 {%0, %1}, %2;" : "=f"(r.x), "=f"(r.y) : "l"(v)); return r;
}
__device__ __forceinline__ void cp16(void* sdst, const void* gsrc) {
    unsigned s = (unsigned)__cvta_generic_to_shared(sdst);
    asm volatile("cp.async.cg.shared.global [%0], [%1], 16;" :: "r"(s), "l"(gsrc) : "memory");
}
__device__ __forceinline__ void cp_commit() {
    asm volatile("cp.async.commit_group;" ::: "memory");
}
__device__ __forceinline__ void cp_wait1() {
    asm volatile("cp.async.wait_group 1;" ::: "memory");
}
__device__ __forceinline__ float neg_inf() { return __int_as_float(0xff800000); }

// Monotonic key: larger value wins; tie -> smaller index wins. Unique per idx.
__device__ __forceinline__ ull make_key(float v, unsigned idx) {
    unsigned u = __float_as_uint(v);
    u = (u & 0x80000000u) ? ~u : (u | 0x80000000u);
    return ((ull)u << 32) | (ull)(~idx);
}
__device__ __forceinline__ float key_val(ull k) {
    unsigned u = (unsigned)(k >> 32);
    u = (u & 0x80000000u) ? (u & 0x7fffffffu) : ~u;
    return __uint_as_float(u);
}
__device__ __forceinline__ unsigned key_idx(ull k) { return ~((unsigned)k); }

// ------------------------------------------------------------------
// Init (clears counters each graph replay)
// ------------------------------------------------------------------
__global__ void init_kernel(const float* __restrict__ enc) {
    int r = blockIdx.x;      // 0..127
    int c = threadIdx.x;     // 0..511
    g_h[0][r * Hd + c] = enc[(r & 15) * Hd + c];
    if (c == 0) {
        g_tokens[r] = SOS_T;
        g_perm[r]   = r;
        g_scores[r] = ((r & 7) == 0) ? 0.0f : neg_inf();
        if (r == 0) { g_ctrL = 0; g_lseCtr = 0; }
    }
}

// ------------------------------------------------------------------
// GRU dual-GEMM, register-prefetch double-buffered (R9 verbatim).
// grid (24, 2, 2), 256 threads, 64x64 tile, 4x4 micro (f32x2)
// ------------------------------------------------------------------
__global__ __launch_bounds__(256) void gru_gemm_kernel(
    const float* __restrict__ emb,
    const float* __restrict__ w_ih, const float* __restrict__ w_hh,
    const float* __restrict__ b_ih, const float* __restrict__ b_hh,
    int cur)
{
    const int which = blockIdx.z;
    const int m0 = blockIdx.y * 64;
    const int n0 = blockIdx.x * 64;
    const float* A  = which ? &g_h[cur][0] : emb;
    const float* W  = which ? w_hh : w_ih;
    const float* bv = which ? b_hh : b_ih;
    float* outp     = which ? g_gh : g_gi;

    __shared__ int idx_s[64];
    __shared__ __align__(16) float As[2][16][68];
    __shared__ __align__(16) float Bs[2][16][68];

    const int tid = threadIdx.x;
    if (tid < 64) {
        int r = m0 + tid;
        idx_s[tid] = (which ? g_perm[r] : g_tokens[r]) * Hd;
    }
    __syncthreads();

    const int tx = tid & 15, ty = tid >> 4;
    const int lr = tid >> 2;                 // 0..63
    const int lk = (tid & 3) * 4;            // 0,4,8,12
    const size_t aoff = (size_t)idx_s[lr];
    const size_t woff = (size_t)(n0 + lr) * Hd;

    ull c2[4][2];
#pragma unroll
    for (int i = 0; i < 4; i++) { c2[i][0] = 0ULL; c2[i][1] = 0ULL; }

    float4 av = *(const float4*)(A + aoff + lk);
    float4 bw = *(const float4*)(W + woff + lk);
    As[0][lk + 0][lr] = av.x; As[0][lk + 1][lr] = av.y;
    As[0][lk + 2][lr] = av.z; As[0][lk + 3][lr] = av.w;
    Bs[0][lk + 0][lr] = bw.x; Bs[0][lk + 1][lr] = bw.y;
    Bs[0][lk + 2][lr] = bw.z; Bs[0][lk + 3][lr] = bw.w;

#pragma unroll 1
    for (int ks = 0; ks < 32; ks++) {
        const int buf = ks & 1;
        __syncthreads();
        if (ks < 31) {
            const int k1 = (ks + 1) * 16;
            av = *(const float4*)(A + aoff + k1 + lk);
            bw = *(const float4*)(W + woff + k1 + lk);
        }
#pragma unroll
        for (int k = 0; k < 16; k++) {
            float4 a = *(const float4*)&As[buf][k][ty * 4];
            ulonglong2 b = *(const ulonglong2*)&Bs[buf][k][tx * 4];
            ull aa0 = pack2(a.x, a.x), aa1 = pack2(a.y, a.y);
            ull aa2 = pack2(a.z, a.z), aa3 = pack2(a.w, a.w);
            ffma2(c2[0][0], aa0, b.x); ffma2(c2[0][1], aa0, b.y);
            ffma2(c2[1][0], aa1, b.x); ffma2(c2[1][1], aa1, b.y);
            ffma2(c2[2][0], aa2, b.x); ffma2(c2[2][1], aa2, b.y);
            ffma2(c2[3][0], aa3, b.x); ffma2(c2[3][1], aa3, b.y);
        }
        if (ks < 31) {
            const int nb = buf ^ 1;
            As[nb][lk + 0][lr] = av.x; As[nb][lk + 1][lr] = av.y;
            As[nb][lk + 2][lr] = av.z; As[nb][lk + 3][lr] = av.w;
            Bs[nb][lk + 0][lr] = bw.x; Bs[nb][lk + 1][lr] = bw.y;
            Bs[nb][lk + 2][lr] = bw.z; Bs[nb][lk + 3][lr] = bw.w;
        }
    }

    const int nb = n0 + tx * 4;
    float4 bias4 = *(const float4*)&bv[nb];
#pragma unroll
    for (int i = 0; i < 4; i++) {
        float2 p0 = unpack2(c2[i][0]);
        float2 p1 = unpack2(c2[i][1]);
        float4 o;
        o.x = p0.x + bias4.x; o.y = p0.y + bias4.y;
        o.z = p1.x + bias4.z; o.w = p1.y + bias4.w;
        int m = m0 + ty * 4 + i;
        *(float4*)&outp[(size_t)m * G3H + nb] = o;
    }
}

// ------------------------------------------------------------------
// GRU gate combine (R9 verbatim)
// ------------------------------------------------------------------
__global__ void gru_combine_kernel(int cur) {
    int row = blockIdx.x;
    int col = threadIdx.x;
    int rp = g_perm[row];
    float hprev = g_h[cur][rp * Hd + col];
    size_t base = (size_t)row * G3H;
    float ir = g_gi[base + col];
    float iz = g_gi[base + Hd + col];
    float in_ = g_gi[base + 2 * Hd + col];
    float hr = g_gh[base + col];
    float hz = g_gh[base + Hd + col];
    float hn = g_gh[base + 2 * Hd + col];
    float r = 1.0f / (1.0f + expf(-(ir + hr)));
    float z = 1.0f / (1.0f + expf(-(iz + hz)));
    float n = tanhf(in_ + r * hn);
    float h = (1.0f - z) * n + z * hprev;
    g_h[1 - cur][row * Hd + col] = h;
    g_hT[col * BK + row] = h;
}

// ------------------------------------------------------------------
// Logits GEMM + in-kernel LSE + logp write + per-(row,tile) top-8.
// 250 CTAs (all co-resident: 2/SM <= 296 capacity), 256 threads.
// Main loop & partial reductions byte-identical to R9/R13 (bit-exact).
// Epilogue publishes only pmax/psum (64B/CTA), grid-syncs, 8 designated
// CTAs run the verbatim R12 lse fold (smem reused from dead As/Bs),
// then every CTA recomputes v = c2+bias (bit-identical), writes
// logp = v - lse directly, and emits exact top-8 keys per (row, tile).
// ------------------------------------------------------------------
__global__ __launch_bounds__(256, 2) void logits_kernel(
    const float* __restrict__ W, const float* __restrict__ bias,
    float* __restrict__ out_logp, int t)
{
    __shared__ __align__(16) float As[2][16][128];
    __shared__ __align__(16) float Bs[2][16][128];

    const int tid = threadIdx.x;
    const int bx  = blockIdx.x;
    const int n0  = bx * 128;
    const int tx  = tid & 15, ty = tid >> 4;
    const float* hT = g_hT;

    ull c2[8][4];
#pragma unroll
    for (int i = 0; i < 8; i++)
#pragma unroll
        for (int j = 0; j < 4; j++) c2[i][j] = 0ULL;

    auto stage = [&](int ks, int buf) {
        const int k0 = ks * 16;
#pragma unroll
        for (int u = 0; u < 2; u++) {
            int f = tid + u * 256;
            int k = f >> 5;
            int c = (f & 31) << 2;
            cp16(&As[buf][k][c], hT + (size_t)(k0 + k) * BK + c);
            cp16(&Bs[buf][k][c], W + (size_t)(k0 + k) * Vv + n0 + c);
        }
    };

    stage(0, 0);
    cp_commit();

#pragma unroll 1
    for (int ks = 0; ks < 32; ks++) {
        const int buf = ks & 1;
        if (ks < 31) stage(ks + 1, buf ^ 1);
        cp_commit();
        cp_wait1();
        __syncthreads();
#pragma unroll
        for (int k = 0; k < 16; k++) {
            float4 a0 = *(const float4*)&As[buf][k][ty * 8];
            float4 a1 = *(const float4*)&As[buf][k][ty * 8 + 4];
            ulonglong2 b01 = *(const ulonglong2*)&Bs[buf][k][tx * 8];
            ulonglong2 b23 = *(const ulonglong2*)&Bs[buf][k][tx * 8 + 4];
            ull b0 = b01.x, b1 = b01.y, b2 = b23.x, b3 = b23.y;
            ull aa[8];
            aa[0] = pack2(a0.x, a0.x); aa[1] = pack2(a0.y, a0.y);
            aa[2] = pack2(a0.z, a0.z); aa[3] = pack2(a0.w, a0.w);
            aa[4] = pack2(a1.x, a1.x); aa[5] = pack2(a1.y, a1.y);
            aa[6] = pack2(a1.z, a1.z); aa[7] = pack2(a1.w, a1.w);
#pragma unroll
            for (int i = 0; i < 8; i++) {
                ffma2(c2[i][0], aa[i], b0);
                ffma2(c2[i][1], aa[i], b1);
                ffma2(c2[i][2], aa[i], b2);
                ffma2(c2[i][3], aa[i], b3);
            }
        }
        __syncthreads();
    }

    // ---- Phase 1: per-tile (max, sumexp) partials (R5 tree verbatim) ----
    const int col0 = n0 + tx * 8;
    float4 bb0 = *(const float4*)&bias[col0];
    float4 bb1 = *(const float4*)&bias[col0 + 4];
#pragma unroll
    for (int i = 0; i < 8; i++) {
        float2 p0 = unpack2(c2[i][0]);
        float2 p1 = unpack2(c2[i][1]);
        float2 p2 = unpack2(c2[i][2]);
        float2 p3 = unpack2(c2[i][3]);
        float v0 = p0.x + bb0.x, v1 = p0.y + bb0.y;
        float v2 = p1.x + bb0.z, v3 = p1.y + bb0.w;
        float v4 = p2.x + bb1.x, v5 = p2.y + bb1.y;
        float v6 = p3.x + bb1.z, v7 = p3.y + bb1.w;
        int row = ty * 8 + i;

        float m = fmaxf(fmaxf(fmaxf(v0, v1), fmaxf(v2, v3)),
                        fmaxf(fmaxf(v4, v5), fmaxf(v6, v7)));
#pragma unroll
        for (int off = 8; off >= 1; off >>= 1)
            m = fmaxf(m, __shfl_xor_sync(0xffffffffu, m, off, 16));
        float s = __expf(v0 - m) + __expf(v1 - m) + __expf(v2 - m) + __expf(v3 - m)
                + __expf(v4 - m) + __expf(v5 - m) + __expf(v6 - m) + __expf(v7 - m);
#pragma unroll
        for (int off = 8; off >= 1; off >>= 1)
            s += __shfl_xor_sync(0xffffffffu, s, off, 16);
        if (tx == 0) {
            g_pmax[bx * BK + row] = m;
            g_psum[bx * BK + row] = s;
        }
    }

    // ---- grid arrival (only 64B of stores to drain) ----
    __threadfence();
    __syncthreads();
    if (tid == 0) atomicAdd(&g_ctrL, 1);

    // ---- Phase 2: designated CTAs compute lse slices (R12 verbatim) ----
    if (bx < 8) {
        float* spmax = &As[0][0][0];   // 4096 floats free (main loop done)
        float* spsum = &Bs[0][0][0];
        if (tid == 0) {
            while (atomicAdd(&g_ctrL, 0) < (t + 1) * NT) __nanosleep(32);
        }
        __syncthreads();
        __threadfence();
        const int r0 = bx * 16;
        for (int idx = tid; idx < NT * 16; idx += 256) {
            int j = idx >> 4;
            int i2 = idx & 15;
            spmax[idx] = g_pmax[j * BK + r0 + i2];
            spsum[idx] = g_psum[j * BK + r0 + i2];
        }
        __syncthreads();
        if (tid < 16) {
            const int i2 = tid;
            float m = neg_inf();
#pragma unroll 5
            for (int j = 0; j < NT; j++) m = fmaxf(m, spmax[j * 16 + i2]);
            float s = 0.0f;
#pragma unroll 5
            for (int j = 0; j < NT; j++)
                s += spsum[j * 16 + i2] * __expf(spmax[j * 16 + i2] - m);
            g_lse[r0 + i2] = m + logf(s);
        }
        __threadfence();
        __syncthreads();
        if (tid == 0) atomicAdd(&g_lseCtr, 1);
    }

    // ---- all CTAs wait for lse ----
    if (tid == 0) {
        while (atomicAdd(&g_lseCtr, 0) < (t + 1) * 8) __nanosleep(32);
    }
    __syncthreads();
    __threadfence();

    // ---- Phase 3: logp write + exact per-(row,tile) top-8 keys ----
#pragma unroll 1
    for (int i = 0; i < 8; i++) {
        float2 p0 = unpack2(c2[i][0]);
        float2 p1 = unpack2(c2[i][1]);
        float2 p2 = unpack2(c2[i][2]);
        float2 p3 = unpack2(c2[i][3]);
        float v0 = p0.x + bb0.x, v1 = p0.y + bb0.y;
        float v2 = p1.x + bb0.z, v3 = p1.y + bb0.w;
        float v4 = p2.x + bb1.x, v5 = p2.y + bb1.y;
        float v6 = p3.x + bb1.z, v7 = p3.y + bb1.w;
        const int row = ty * 8 + i;
        const float lse = g_lse[row];
        const float sc  = g_scores[row];
        const float l0 = v0 - lse, l1 = v1 - lse, l2 = v2 - lse, l3 = v3 - lse;
        const float l4 = v4 - lse, l5 = v5 - lse, l6 = v6 - lse, l7 = v7 - lse;
        *(float4*)&out_logp[(size_t)row * Vv + col0]     = make_float4(l0, l1, l2, l3);
        *(float4*)&out_logp[(size_t)row * Vv + col0 + 4] = make_float4(l4, l5, l6, l7);

        const unsigned ibase = (unsigned)((row & 7) * Vv + col0);
        ull key[8];
        key[0] = make_key(sc + l0, ibase + 0);
        key[1] = make_key(sc + l1, ibase + 1);
        key[2] = make_key(sc + l2, ibase + 2);
        key[3] = make_key(sc + l3, ibase + 3);
        key[4] = make_key(sc + l4, ibase + 4);
        key[5] = make_key(sc + l5, ibase + 5);
        key[6] = make_key(sc + l6, ibase + 6);
        key[7] = make_key(sc + l7, ibase + 7);

        ull* dst = &g_ckeyN[((size_t)row * NT + bx) * 8];
#pragma unroll 1
        for (int round = 0; round < 8; round++) {
            ull loc = key[0];
#pragma unroll
            for (int j = 1; j < 8; j++) if (key[j] > loc) loc = key[j];
#pragma unroll
            for (int off = 8; off >= 1; off >>= 1) {
                ull o = __shfl_xor_sync(0xffffffffu, loc, off, 16);
                if (o > loc) loc = o;
            }
            if (tx == 0) dst[round] = loc;
#pragma unroll
            for (int j = 0; j < 8; j++) if (key[j] == loc) key[j] = 0ULL;
        }
    }
}

// ------------------------------------------------------------------
// Merge: one block per batch; exact top-8 of 8 rows x 250 tiles x 8 keys.
// Writes scores/syms/preds and updates tokens/seq_scores/perm.
// ------------------------------------------------------------------
__global__ __launch_bounds__(256) void merge_kernel(
    float* out_scores, float* out_syms, float* out_preds)
{
    const int b    = blockIdx.x;       // batch
    const int tid  = threadIdx.x;
    const int w    = tid >> 5;         // 8 warps
    const int lane = tid & 31;
    const ull* keys = &g_ckeyN[(size_t)b * 8 * NT * 8];   // 16000 contiguous

    ull L[8];
#pragma unroll
    for (int i = 0; i < 8; i++) L[i] = 0ULL;
    for (int j = tid; j < 8 * NT * 8; j += 256) {
        ull k = keys[j];
        if (k > L[7]) {
            L[7] = k;
#pragma unroll
            for (int i = 7; i > 0; i--)
                if (L[i] > L[i - 1]) { ull tv = L[i - 1]; L[i - 1] = L[i]; L[i] = tv; }
        }
    }

    __shared__ ull wm[8 * 8];
    for (int k = 0; k < 8; k++) {
        ull mx = L[0];
#pragma unroll
        for (int off = 16; off >= 1; off >>= 1) {
            ull o = __shfl_xor_sync(0xffffffffu, mx, off);
            if (o > mx) mx = o;
        }
        if (L[0] == mx) {   // unique keys -> one lane pops
            L[0] = L[1]; L[1] = L[2]; L[2] = L[3]; L[3] = L[4];
            L[4] = L[5]; L[5] = L[6]; L[6] = L[7]; L[7] = 0ULL;
        }
        if (lane == 0) wm[w * 8 + k] = mx;
    }
    __syncthreads();

    if (w == 0) {
        ull k2[2];
        k2[0] = wm[lane * 2];
        k2[1] = wm[lane * 2 + 1];
        for (int k = 0; k < 8; k++) {
            ull loc = (k2[0] > k2[1]) ? k2[0] : k2[1];
#pragma unroll
            for (int off = 16; off >= 1; off >>= 1) {
                ull o = __shfl_xor_sync(0xffffffffu, loc, off);
                if (o > loc) loc = o;
            }
            if (lane == 0) {
                float val = key_val(loc);
                unsigned idx = key_idx(loc);
                int token = (int)(idx % (unsigned)Vv);
                int beam  = (int)(idx / (unsigned)Vv);
                int orow  = b * 8 + k;
                int pred  = b * 8 + beam;
                if (out_scores) {
                    out_scores[orow] = val;           // pre-EOS-mask
                    out_syms[orow]   = (float)token;
                    out_preds[orow]  = (float)pred;
                }
                g_tokens[orow] = token;
                g_scores[orow] = (token == EOS_T) ? neg_inf() : val;
                g_perm[orow]   = pred;
            }
#pragma unroll
            for (int j = 0; j < 2; j++) if (k2[j] == loc) k2[j] = 0ULL;
        }
    }
}

// ------------------------------------------------------------------
__global__ void final_kernel(float* __restrict__ out_hidden) {
    int row = blockIdx.x;
    int c = threadIdx.x;
    out_hidden[row * Hd + c] = g_h[0][g_perm[row] * Hd + c];
}

// ------------------------------------------------------------------
extern "C" void kernel_launch(void* const* d_in, const int* in_sizes, int n_in,
                              void* d_out, int out_size) {
    const float* enc   = (const float*)d_in[0];
    const float* emb   = (const float*)d_in[1];
    const float* w_ih  = (const float*)d_in[2];
    const float* w_hh  = (const float*)d_in[3];
    const float* b_ih  = (const float*)d_in[4];
    const float* b_hh  = (const float*)d_in[5];
    const float* w_out = (const float*)d_in[6];
    const float* b_out = (const float*)d_in[7];

    float* out = (float*)d_out;
    const size_t outs_sz = (size_t)Tt * BK * Vv;
    const size_t total   = outs_sz + 3 * (size_t)Tt * BK + (size_t)BK * Hd;
    const bool has_tail  = ((size_t)(unsigned)out_size >= total);

    float* out_logp   = out;
    float* out_scores = has_tail ? out + outs_sz : nullptr;
    float* out_syms   = has_tail ? out_scores + Tt * BK : nullptr;
    float* out_preds  = has_tail ? out_syms + Tt * BK : nullptr;
    float* out_hidden = has_tail ? out_preds + Tt * BK : nullptr;

    init_kernel<<<BK, Hd>>>(enc);

    for (int t = 0; t < Tt; t++) {
        int cur = t & 1;
        gru_gemm_kernel<<<dim3(24, 2, 2), 256>>>(emb, w_ih, w_hh, b_ih, b_hh, cur);
        gru_combine_kernel<<<BK, Hd>>>(cur);

        float* logits_t = out_logp + (size_t)t * BK * Vv;
        logits_kernel<<<NT, 256>>>(w_out, b_out, logits_t, t);
        merge_kernel<<<Bb, 256>>>(
            has_tail ? out_scores + (size_t)t * BK : nullptr,
            has_tail ? out_syms   + (size_t)t * BK : nullptr,
            has_tail ? out_preds  + (size_t)t * BK : nullptr);
    }

    if (has_tail) final_kernel<<<BK, Hd>>>(out_hidden);
}

// round 15
// speedup vs baseline: 1.2722x; 1.2722x over previous
#include <cuda_runtime.h>
#include <math.h>
#include <stdint.h>

typedef unsigned long long ull;

#define Bb     16
#define Vv     32000
#define Hd     512
#define BK     128          // B*K rows
#define Tt     32
#define NT     250          // logits CTAs / partial tiles of 128 cols
#define NT2    125          // pass2 CTAs (256-col tiles)
#define G3H    1536
#define SOS_T  1
#define EOS_T  2

// ------------------------------------------------------------------
// Persistent device state (no cudaMalloc allowed)
// ------------------------------------------------------------------
__device__ float g_h[2][BK * Hd];       // hidden ping-pong
__device__ float g_hT[Hd * BK];         // transposed h_new for logits A-tiles
__device__ float g_gi[BK * G3H];
__device__ float g_gh[BK * G3H];
__device__ float g_pmax[NT * BK];       // per-128-col-tile row max  [tile][row]
__device__ float g_psum[NT * BK];       // per-128-col-tile row sumexp [tile][row]
__device__ float g_lse[BK];
__device__ int   g_tokens[BK];
__device__ int   g_perm[BK];
__device__ float g_scores[BK];
__device__ ull   g_ckey[Bb * NT2 * 8];  // per-(batch,256-tile) top-8 keys
__device__ int   g_ctrB;                // pass2 last-block counter (self-resetting)
__device__ int   g_lseCtr;              // lse arrival counter (monotonic per replay)

// ------------------------------------------------------------------
// Helpers
// ------------------------------------------------------------------
__device__ __forceinline__ ull pack2(float x, float y) {
    ull r; asm("mov.b64 %0, {%1, %2};" : "=l"(r) : "f"(x), "f"(y)); return r;
}
__device__ __forceinline__ void ffma2(ull& d, ull a, ull b) {
    asm("fma.rn.f32x2 %0, %1, %2, %0;" : "+l"(d) : "l"(a), "l"(b));
}
__device__ __forceinline__ float2 unpack2(ull v) {
    float2 r; asm("mov.b64 {%0, %1}, %2;" : "=f"(r.x), "=f"(r.y) : "l"(v)); return r;
}
__device__ __forceinline__ void cp16(void* sdst, const void* gsrc) {
    unsigned s = (unsigned)__cvta_generic_to_shared(sdst);
    asm volatile("cp.async.cg.shared.global [%0], [%1], 16;" :: "r"(s), "l"(gsrc) : "memory");
}
__device__ __forceinline__ void cp_commit() {
    asm volatile("cp.async.commit_group;" ::: "memory");
}
__device__ __forceinline__ void cp_wait1() {
    asm volatile("cp.async.wait_group 1;" ::: "memory");
}
__device__ __forceinline__ float neg_inf() { return __int_as_float(0xff800000); }

// Monotonic key: larger value wins; tie -> smaller index wins. Unique per idx.
__device__ __forceinline__ ull make_key(float v, unsigned idx) {
    unsigned u = __float_as_uint(v);
    u = (u & 0x80000000u) ? ~u : (u | 0x80000000u);
    return ((ull)u << 32) | (ull)(~idx);
}
__device__ __forceinline__ float key_val(ull k) {
    unsigned u = (unsigned)(k >> 32);
    u = (u & 0x80000000u) ? (u & 0x7fffffffu) : ~u;
    return __uint_as_float(u);
}
__device__ __forceinline__ unsigned key_idx(ull k) { return ~((unsigned)k); }

// ------------------------------------------------------------------
// Init (clears counters each graph replay)
// ------------------------------------------------------------------
__global__ void init_kernel(const float* __restrict__ enc) {
    int r = blockIdx.x;      // 0..127
    int c = threadIdx.x;     // 0..511
    g_h[0][r * Hd + c] = enc[(r & 15) * Hd + c];
    if (c == 0) {
        g_tokens[r] = SOS_T;
        g_perm[r]   = r;
        g_scores[r] = ((r & 7) == 0) ? 0.0f : neg_inf();
        if (r == 0) { g_ctrB = 0; g_lseCtr = 0; }
    }
}

// ------------------------------------------------------------------
// GRU dual-GEMM, register-prefetch double-buffered (R9 verbatim).
// grid (24, 2, 2), 256 threads, 64x64 tile, 4x4 micro (f32x2)
// ------------------------------------------------------------------
__global__ __launch_bounds__(256) void gru_gemm_kernel(
    const float* __restrict__ emb,
    const float* __restrict__ w_ih, const float* __restrict__ w_hh,
    const float* __restrict__ b_ih, const float* __restrict__ b_hh,
    int cur)
{
    const int which = blockIdx.z;
    const int m0 = blockIdx.y * 64;
    const int n0 = blockIdx.x * 64;
    const float* A  = which ? &g_h[cur][0] : emb;
    const float* W  = which ? w_hh : w_ih;
    const float* bv = which ? b_hh : b_ih;
    float* outp     = which ? g_gh : g_gi;

    __shared__ int idx_s[64];
    __shared__ __align__(16) float As[2][16][68];
    __shared__ __align__(16) float Bs[2][16][68];

    const int tid = threadIdx.x;
    if (tid < 64) {
        int r = m0 + tid;
        idx_s[tid] = (which ? g_perm[r] : g_tokens[r]) * Hd;
    }
    __syncthreads();

    const int tx = tid & 15, ty = tid >> 4;
    const int lr = tid >> 2;                 // 0..63
    const int lk = (tid & 3) * 4;            // 0,4,8,12
    const size_t aoff = (size_t)idx_s[lr];
    const size_t woff = (size_t)(n0 + lr) * Hd;

    ull c2[4][2];
#pragma unroll
    for (int i = 0; i < 4; i++) { c2[i][0] = 0ULL; c2[i][1] = 0ULL; }

    float4 av = *(const float4*)(A + aoff + lk);
    float4 bw = *(const float4*)(W + woff + lk);
    As[0][lk + 0][lr] = av.x; As[0][lk + 1][lr] = av.y;
    As[0][lk + 2][lr] = av.z; As[0][lk + 3][lr] = av.w;
    Bs[0][lk + 0][lr] = bw.x; Bs[0][lk + 1][lr] = bw.y;
    Bs[0][lk + 2][lr] = bw.z; Bs[0][lk + 3][lr] = bw.w;

#pragma unroll 1
    for (int ks = 0; ks < 32; ks++) {
        const int buf = ks & 1;
        __syncthreads();
        if (ks < 31) {
            const int k1 = (ks + 1) * 16;
            av = *(const float4*)(A + aoff + k1 + lk);
            bw = *(const float4*)(W + woff + k1 + lk);
        }
#pragma unroll
        for (int k = 0; k < 16; k++) {
            float4 a = *(const float4*)&As[buf][k][ty * 4];
            ulonglong2 b = *(const ulonglong2*)&Bs[buf][k][tx * 4];
            ull aa0 = pack2(a.x, a.x), aa1 = pack2(a.y, a.y);
            ull aa2 = pack2(a.z, a.z), aa3 = pack2(a.w, a.w);
            ffma2(c2[0][0], aa0, b.x); ffma2(c2[0][1], aa0, b.y);
            ffma2(c2[1][0], aa1, b.x); ffma2(c2[1][1], aa1, b.y);
            ffma2(c2[2][0], aa2, b.x); ffma2(c2[2][1], aa2, b.y);
            ffma2(c2[3][0], aa3, b.x); ffma2(c2[3][1], aa3, b.y);
        }
        if (ks < 31) {
            const int nb = buf ^ 1;
            As[nb][lk + 0][lr] = av.x; As[nb][lk + 1][lr] = av.y;
            As[nb][lk + 2][lr] = av.z; As[nb][lk + 3][lr] = av.w;
            Bs[nb][lk + 0][lr] = bw.x; Bs[nb][lk + 1][lr] = bw.y;
            Bs[nb][lk + 2][lr] = bw.z; Bs[nb][lk + 3][lr] = bw.w;
        }
    }

    const int nb = n0 + tx * 4;
    float4 bias4 = *(const float4*)&bv[nb];
#pragma unroll
    for (int i = 0; i < 4; i++) {
        float2 p0 = unpack2(c2[i][0]);
        float2 p1 = unpack2(c2[i][1]);
        float4 o;
        o.x = p0.x + bias4.x; o.y = p0.y + bias4.y;
        o.z = p1.x + bias4.z; o.w = p1.y + bias4.w;
        int m = m0 + ty * 4 + i;
        *(float4*)&outp[(size_t)m * G3H + nb] = o;
    }
}

// ------------------------------------------------------------------
// GRU gate combine (R9 verbatim)
// ------------------------------------------------------------------
__global__ void gru_combine_kernel(int cur) {
    int row = blockIdx.x;
    int col = threadIdx.x;
    int rp = g_perm[row];
    float hprev = g_h[cur][rp * Hd + col];
    size_t base = (size_t)row * G3H;
    float ir = g_gi[base + col];
    float iz = g_gi[base + Hd + col];
    float in_ = g_gi[base + 2 * Hd + col];
    float hr = g_gh[base + col];
    float hz = g_gh[base + Hd + col];
    float hn = g_gh[base + 2 * Hd + col];
    float r = 1.0f / (1.0f + expf(-(ir + hr)));
    float z = 1.0f / (1.0f + expf(-(iz + hz)));
    float n = tanhf(in_ + r * hn);
    float h = (1.0f - z) * n + z * hprev;
    g_h[1 - cur][row * Hd + col] = h;
    g_hT[col * BK + row] = h;
}

// ------------------------------------------------------------------
// Logits GEMM (R9 verbatim, ~98us, FROZEN): [128,512]@[512,32000]+bias.
// 250 CTAs x (128x128 tile), 256 threads, 2 CTAs/SM, KC=16 double-buffered
// cp.async, 8x8 micro in f32x2. No fused tail (R8/R14 lesson).
// ------------------------------------------------------------------
__global__ __launch_bounds__(256, 2) void logits_kernel(
    const float* __restrict__ W, const float* __restrict__ bias,
    float* __restrict__ out_logits)
{
    __shared__ __align__(16) float As[2][16][128];
    __shared__ __align__(16) float Bs[2][16][128];

    const int tid = threadIdx.x;
    const int bx  = blockIdx.x;
    const int n0  = bx * 128;
    const int tx  = tid & 15, ty = tid >> 4;
    const float* hT = g_hT;

    ull c2[8][4];
#pragma unroll
    for (int i = 0; i < 8; i++)
#pragma unroll
        for (int j = 0; j < 4; j++) c2[i][j] = 0ULL;

    auto stage = [&](int ks, int buf) {
        const int k0 = ks * 16;
#pragma unroll
        for (int u = 0; u < 2; u++) {
            int f = tid + u * 256;
            int k = f >> 5;
            int c = (f & 31) << 2;
            cp16(&As[buf][k][c], hT + (size_t)(k0 + k) * BK + c);
            cp16(&Bs[buf][k][c], W + (size_t)(k0 + k) * Vv + n0 + c);
        }
    };

    stage(0, 0);
    cp_commit();

#pragma unroll 1
    for (int ks = 0; ks < 32; ks++) {
        const int buf = ks & 1;
        if (ks < 31) stage(ks + 1, buf ^ 1);
        cp_commit();
        cp_wait1();
        __syncthreads();
#pragma unroll
        for (int k = 0; k < 16; k++) {
            float4 a0 = *(const float4*)&As[buf][k][ty * 8];
            float4 a1 = *(const float4*)&As[buf][k][ty * 8 + 4];
            ulonglong2 b01 = *(const ulonglong2*)&Bs[buf][k][tx * 8];
            ulonglong2 b23 = *(const ulonglong2*)&Bs[buf][k][tx * 8 + 4];
            ull b0 = b01.x, b1 = b01.y, b2 = b23.x, b3 = b23.y;
            ull aa[8];
            aa[0] = pack2(a0.x, a0.x); aa[1] = pack2(a0.y, a0.y);
            aa[2] = pack2(a0.z, a0.z); aa[3] = pack2(a0.w, a0.w);
            aa[4] = pack2(a1.x, a1.x); aa[5] = pack2(a1.y, a1.y);
            aa[6] = pack2(a1.z, a1.z); aa[7] = pack2(a1.w, a1.w);
#pragma unroll
            for (int i = 0; i < 8; i++) {
                ffma2(c2[i][0], aa[i], b0);
                ffma2(c2[i][1], aa[i], b1);
                ffma2(c2[i][2], aa[i], b2);
                ffma2(c2[i][3], aa[i], b3);
            }
        }
        __syncthreads();
    }

    // Epilogue (R5 reduction tree verbatim; partials transposed [tile][row])
    const int col0 = n0 + tx * 8;
    float4 bb0 = *(const float4*)&bias[col0];
    float4 bb1 = *(const float4*)&bias[col0 + 4];
#pragma unroll
    for (int i = 0; i < 8; i++) {
        float2 p0 = unpack2(c2[i][0]);
        float2 p1 = unpack2(c2[i][1]);
        float2 p2 = unpack2(c2[i][2]);
        float2 p3 = unpack2(c2[i][3]);
        float v0 = p0.x + bb0.x, v1 = p0.y + bb0.y;
        float v2 = p1.x + bb0.z, v3 = p1.y + bb0.w;
        float v4 = p2.x + bb1.x, v5 = p2.y + bb1.y;
        float v6 = p3.x + bb1.z, v7 = p3.y + bb1.w;
        int row = ty * 8 + i;
        float4 w0 = make_float4(v0, v1, v2, v3);
        float4 w1 = make_float4(v4, v5, v6, v7);
        *(float4*)&out_logits[(size_t)row * Vv + col0]     = w0;
        *(float4*)&out_logits[(size_t)row * Vv + col0 + 4] = w1;

        float m = fmaxf(fmaxf(fmaxf(v0, v1), fmaxf(v2, v3)),
                        fmaxf(fmaxf(v4, v5), fmaxf(v6, v7)));
#pragma unroll
        for (int off = 8; off >= 1; off >>= 1)
            m = fmaxf(m, __shfl_xor_sync(0xffffffffu, m, off, 16));
        float s = __expf(v0 - m) + __expf(v1 - m) + __expf(v2 - m) + __expf(v3 - m)
                + __expf(v4 - m) + __expf(v5 - m) + __expf(v6 - m) + __expf(v7 - m);
#pragma unroll
        for (int off = 8; off >= 1; off >>= 1)
            s += __shfl_xor_sync(0xffffffffu, s, off, 16);
        if (tx == 0) {
            g_pmax[bx * BK + row] = m;
            g_psum[bx * BK + row] = s;
        }
    }
}

// ------------------------------------------------------------------
// Pass 2 + inline LSE (overlap) + fused final merge.
// grid (125, 16), 512 threads.
// R13 verbatim EXCEPT: the 16KB logp store per block is issued AFTER
// candidate publication + fence + arrival, so the fence no longer has
// to drain it (values and selection bit-identical; ordering only).
// ------------------------------------------------------------------
__global__ __launch_bounds__(512) void pass2_kernel(
    float* __restrict__ logits,
    float* out_scores, float* out_syms, float* out_preds, int t)
{
    const int bx = blockIdx.x;
    const int b  = blockIdx.y;
    const int tid  = threadIdx.x;
    const int w    = tid >> 5;     // 16 warps
    const int lane = tid & 31;
    const int r    = w & 7;        // beam
    const int half = w >> 3;       // col half
    const int row  = b * 8 + r;
    const int vcol = bx * 256 + half * 128 + lane * 4;

    // Prefetch logits BEFORE any lse wait (overlaps spin with memory)
    float4 v = *(float4*)&logits[(size_t)row * Vv + vcol];

    // --- inline LSE: 8 designated wave-1 blocks, verbatim R12 numerics ---
    __shared__ float spmax[NT * 16];
    __shared__ float spsum[NT * 16];

    if (b == 0 && bx < 8) {
        const int r0 = bx * 16;
        for (int idx = tid; idx < NT * 16; idx += 512) {
            int j = idx >> 4;
            int i = idx & 15;
            spmax[idx] = g_pmax[j * BK + r0 + i];
            spsum[idx] = g_psum[j * BK + r0 + i];
        }
        __syncthreads();
        if (tid < 16) {
            const int i = tid;
            float m = neg_inf();
#pragma unroll 5
            for (int j = 0; j < NT; j++) m = fmaxf(m, spmax[j * 16 + i]);
            float s = 0.0f;
#pragma unroll 5
            for (int j = 0; j < NT; j++)
                s += spsum[j * 16 + i] * __expf(spmax[j * 16 + i] - m);
            g_lse[r0 + i] = m + logf(s);
        }
        __threadfence();
        __syncthreads();
        if (tid == 0) atomicAdd(&g_lseCtr, 1);
    }

    // All blocks wait until all 8 lse slices for step t are published
    if (tid == 0) {
        const int target = (t + 1) * 8;
        while (atomicAdd(&g_lseCtr, 0) < target) __nanosleep(32);
    }
    __syncthreads();
    __threadfence();

    float lse = g_lse[row];
    float sc  = g_scores[row];

    v.x -= lse; v.y -= lse; v.z -= lse; v.w -= lse;
    // NOTE: logp store deferred to after candidate publication (see below)

    ull key[4];
    key[0] = make_key(sc + v.x, (unsigned)(r * Vv + vcol + 0));
    key[1] = make_key(sc + v.y, (unsigned)(r * Vv + vcol + 1));
    key[2] = make_key(sc + v.z, (unsigned)(r * Vv + vcol + 2));
    key[3] = make_key(sc + v.w, (unsigned)(r * Vv + vcol + 3));

    __shared__ ull wtop[16 * 8];

    // per-warp top-8 (warp-local only, no block syncs)
#pragma unroll 1
    for (int round = 0; round < 8; round++) {
        ull loc = key[0];
        if (key[1] > loc) loc = key[1];
        if (key[2] > loc) loc = key[2];
        if (key[3] > loc) loc = key[3];
#pragma unroll
        for (int off = 16; off >= 1; off >>= 1) {
            ull o = __shfl_xor_sync(0xffffffffu, loc, off);
            if (o > loc) loc = o;
        }
        if (lane == 0) wtop[w * 8 + round] = loc;
#pragma unroll
        for (int j = 0; j < 4; j++) if (key[j] == loc) key[j] = 0ULL;
    }
    __syncthreads();

    // warp 0 merges the 128 survivors -> exact block top-8
    if (w == 0) {
        ull k4[4];
#pragma unroll
        for (int i = 0; i < 4; i++) k4[i] = wtop[lane * 4 + i];
#pragma unroll 1
        for (int round = 0; round < 8; round++) {
            ull loc = k4[0];
            if (k4[1] > loc) loc = k4[1];
            if (k4[2] > loc) loc = k4[2];
            if (k4[3] > loc) loc = k4[3];
#pragma unroll
            for (int off = 16; off >= 1; off >>= 1) {
                ull o = __shfl_xor_sync(0xffffffffu, loc, off);
                if (o > loc) loc = o;
            }
            if (lane == 0) g_ckey[((size_t)b * NT2 + bx) * 8 + round] = loc;
#pragma unroll
            for (int j = 0; j < 4; j++) if (k4[j] == loc) k4[j] = 0ULL;
        }
    }

    // Fence + arrival BEFORE the bulk logp store: only g_ckey (<=128B)
    // needs to drain here, not 16KB of logp.
    __threadfence();
    __syncthreads();
    __shared__ int amLast;
    if (tid == 0) amLast = (atomicAdd(&g_ctrB, 1) == NT2 * Bb - 1);

    // Deferred logp store (same values, same addresses as R13)
    *(float4*)&logits[(size_t)row * Vv + vcol] = v;

    __syncthreads();
    if (!amLast) return;
    __threadfence();
    if (tid == 0) g_ctrB = 0;

    // warp w = batch w: top-8 of its 1000 candidates
    ull L[8];
#pragma unroll
    for (int i = 0; i < 8; i++) L[i] = 0ULL;
    const int base = w * (NT2 * 8);
    for (int j = lane; j < NT2 * 8; j += 32) {
        ull k = g_ckey[base + j];
        if (k > L[7]) {
            L[7] = k;
#pragma unroll
            for (int i = 7; i > 0; i--)
                if (L[i] > L[i - 1]) { ull tv = L[i - 1]; L[i - 1] = L[i]; L[i] = tv; }
        }
    }
    for (int k = 0; k < 8; k++) {
        ull mx = L[0];
#pragma unroll
        for (int off = 16; off >= 1; off >>= 1) {
            ull o = __shfl_xor_sync(0xffffffffu, mx, off);
            if (o > mx) mx = o;
        }
        if (L[0] == mx) {   // unique keys -> exactly one lane pops
            L[0] = L[1]; L[1] = L[2]; L[2] = L[3]; L[3] = L[4];
            L[4] = L[5]; L[5] = L[6]; L[6] = L[7]; L[7] = 0ULL;
        }
        if (lane == 0) {
            float val = key_val(mx);
            unsigned idx = key_idx(mx);
            int token = (int)(idx % (unsigned)Vv);
            int beam  = (int)(idx / (unsigned)Vv);
            int orow  = w * 8 + k;
            int pred  = w * 8 + beam;
            if (out_scores) {
                out_scores[orow] = val;           // pre-EOS-mask
                out_syms[orow]   = (float)token;
                out_preds[orow]  = (float)pred;
            }
            g_tokens[orow] = token;
            g_scores[orow] = (token == EOS_T) ? neg_inf() : val;
            g_perm[orow]   = pred;
        }
    }
}

// ------------------------------------------------------------------
__global__ void final_kernel(float* __restrict__ out_hidden) {
    int row = blockIdx.x;
    int c = threadIdx.x;
    out_hidden[row * Hd + c] = g_h[0][g_perm[row] * Hd + c];
}

// ------------------------------------------------------------------
extern "C" void kernel_launch(void* const* d_in, const int* in_sizes, int n_in,
                              void* d_out, int out_size) {
    const float* enc   = (const float*)d_in[0];
    const float* emb   = (const float*)d_in[1];
    const float* w_ih  = (const float*)d_in[2];
    const float* w_hh  = (const float*)d_in[3];
    const float* b_ih  = (const float*)d_in[4];
    const float* b_hh  = (const float*)d_in[5];
    const float* w_out = (const float*)d_in[6];
    const float* b_out = (const float*)d_in[7];

    float* out = (float*)d_out;
    const size_t outs_sz = (size_t)Tt * BK * Vv;
    const size_t total   = outs_sz + 3 * (size_t)Tt * BK + (size_t)BK * Hd;
    const bool has_tail  = ((size_t)(unsigned)out_size >= total);

    float* out_logp   = out;
    float* out_scores = has_tail ? out + outs_sz : nullptr;
    float* out_syms   = has_tail ? out_scores + Tt * BK : nullptr;
    float* out_preds  = has_tail ? out_syms + Tt * BK : nullptr;
    float* out_hidden = has_tail ? out_preds + Tt * BK : nullptr;

    init_kernel<<<BK, Hd>>>(enc);

    for (int t = 0; t < Tt; t++) {
        int cur = t & 1;
        gru_gemm_kernel<<<dim3(24, 2, 2), 256>>>(emb, w_ih, w_hh, b_ih, b_hh, cur);
        gru_combine_kernel<<<BK, Hd>>>(cur);

        float* logits_t = out_logp + (size_t)t * BK * Vv;
        logits_kernel<<<NT, 256>>>(w_out, b_out, logits_t);
        pass2_kernel<<<dim3(NT2, Bb), 512>>>(
            logits_t,
            has_tail ? out_scores + (size_t)t * BK : nullptr,
            has_tail ? out_syms   + (size_t)t * BK : nullptr,
            has_tail ? out_preds  + (size_t)t * BK : nullptr,
            t);
    }

    if (has_tail) final_kernel<<<BK, Hd>>>(out_hidden);
}

// round 16
// speedup vs baseline: 1.2964x; 1.0190x over previous
#include <cuda_runtime.h>
#include <math.h>
#include <stdint.h>

typedef unsigned long long ull;

#define Bb     16
#define Vv     32000
#define Hd     512
#define BK     128          // B*K rows
#define Tt     32
#define NT     250          // col-tiles of 128 / logits grid.x
#define NT2    125          // pass2 CTAs (256-col tiles)
#define G3H    1536
#define SOS_T  1
#define EOS_T  2

// ------------------------------------------------------------------
// Persistent device state (no cudaMalloc allowed)
// ------------------------------------------------------------------
__device__ float g_h[2][BK * Hd];       // hidden ping-pong
__device__ float g_hT[Hd * BK];         // transposed h_new for logits A-tiles
__device__ float g_gi[BK * G3H];
__device__ float g_gh[BK * G3H];
__device__ float g_pmax[NT * BK];       // per-128-col-tile row max  [tile][row]
__device__ float g_psum[NT * BK];       // per-128-col-tile row sumexp [tile][row]
__device__ float g_lse[BK];
__device__ int   g_tokens[BK];
__device__ int   g_perm[BK];
__device__ float g_scores[BK];
__device__ ull   g_ckey[Bb * NT2 * 8];  // per-(batch,256-tile) top-8 keys
__device__ int   g_ctrB;                // pass2 last-block counter (self-resetting)
__device__ int   g_lseCtr;              // lse arrival counter (monotonic per replay)

// ------------------------------------------------------------------
// Helpers
// ------------------------------------------------------------------
__device__ __forceinline__ ull pack2(float x, float y) {
    ull r; asm("mov.b64 %0, {%1, %2};" : "=l"(r) : "f"(x), "f"(y)); return r;
}
__device__ __forceinline__ void ffma2(ull& d, ull a, ull b) {
    asm("fma.rn.f32x2 %0, %1, %2, %0;" : "+l"(d) : "l"(a), "l"(b));
}
__device__ __forceinline__ float2 unpack2(ull v) {
    float2 r; asm("mov.b64 {%0, %1}, %2;" : "=f"(r.x), "=f"(r.y) : "l"(v)); return r;
}
__device__ __forceinline__ void cp16(void* sdst, const void* gsrc) {
    unsigned s = (unsigned)__cvta_generic_to_shared(sdst);
    asm volatile("cp.async.cg.shared.global [%0], [%1], 16;" :: "r"(s), "l"(gsrc) : "memory");
}
__device__ __forceinline__ void cp_commit() {
    asm volatile("cp.async.commit_group;" ::: "memory");
}
__device__ __forceinline__ void cp_wait1() {
    asm volatile("cp.async.wait_group 1;" ::: "memory");
}
__device__ __forceinline__ float neg_inf() { return __int_as_float(0xff800000); }

// Monotonic key: larger value wins; tie -> smaller index wins. Unique per idx.
__device__ __forceinline__ ull make_key(float v, unsigned idx) {
    unsigned u = __float_as_uint(v);
    u = (u & 0x80000000u) ? ~u : (u | 0x80000000u);
    return ((ull)u << 32) | (ull)(~idx);
}
__device__ __forceinline__ float key_val(ull k) {
    unsigned u = (unsigned)(k >> 32);
    u = (u & 0x80000000u) ? (u & 0x7fffffffu) : ~u;
    return __uint_as_float(u);
}
__device__ __forceinline__ unsigned key_idx(ull k) { return ~((unsigned)k); }

// ------------------------------------------------------------------
// Init (clears counters each graph replay)
// ------------------------------------------------------------------
__global__ void init_kernel(const float* __restrict__ enc) {
    int r = blockIdx.x;      // 0..127
    int c = threadIdx.x;     // 0..511
    g_h[0][r * Hd + c] = enc[(r & 15) * Hd + c];
    if (c == 0) {
        g_tokens[r] = SOS_T;
        g_perm[r]   = r;
        g_scores[r] = ((r & 7) == 0) ? 0.0f : neg_inf();
        if (r == 0) { g_ctrB = 0; g_lseCtr = 0; }
    }
}

// ------------------------------------------------------------------
// GRU dual-GEMM, register-prefetch double-buffered (R9 verbatim).
// grid (24, 2, 2), 256 threads, 64x64 tile, 4x4 micro (f32x2)
// ------------------------------------------------------------------
__global__ __launch_bounds__(256) void gru_gemm_kernel(
    const float* __restrict__ emb,
    const float* __restrict__ w_ih, const float* __restrict__ w_hh,
    const float* __restrict__ b_ih, const float* __restrict__ b_hh,
    int cur)
{
    const int which = blockIdx.z;
    const int m0 = blockIdx.y * 64;
    const int n0 = blockIdx.x * 64;
    const float* A  = which ? &g_h[cur][0] : emb;
    const float* W  = which ? w_hh : w_ih;
    const float* bv = which ? b_hh : b_ih;
    float* outp     = which ? g_gh : g_gi;

    __shared__ int idx_s[64];
    __shared__ __align__(16) float As[2][16][68];
    __shared__ __align__(16) float Bs[2][16][68];

    const int tid = threadIdx.x;
    if (tid < 64) {
        int r = m0 + tid;
        idx_s[tid] = (which ? g_perm[r] : g_tokens[r]) * Hd;
    }
    __syncthreads();

    const int tx = tid & 15, ty = tid >> 4;
    const int lr = tid >> 2;                 // 0..63
    const int lk = (tid & 3) * 4;            // 0,4,8,12
    const size_t aoff = (size_t)idx_s[lr];
    const size_t woff = (size_t)(n0 + lr) * Hd;

    ull c2[4][2];
#pragma unroll
    for (int i = 0; i < 4; i++) { c2[i][0] = 0ULL; c2[i][1] = 0ULL; }

    float4 av = *(const float4*)(A + aoff + lk);
    float4 bw = *(const float4*)(W + woff + lk);
    As[0][lk + 0][lr] = av.x; As[0][lk + 1][lr] = av.y;
    As[0][lk + 2][lr] = av.z; As[0][lk + 3][lr] = av.w;
    Bs[0][lk + 0][lr] = bw.x; Bs[0][lk + 1][lr] = bw.y;
    Bs[0][lk + 2][lr] = bw.z; Bs[0][lk + 3][lr] = bw.w;

#pragma unroll 1
    for (int ks = 0; ks < 32; ks++) {
        const int buf = ks & 1;
        __syncthreads();
        if (ks < 31) {
            const int k1 = (ks + 1) * 16;
            av = *(const float4*)(A + aoff + k1 + lk);
            bw = *(const float4*)(W + woff + k1 + lk);
        }
#pragma unroll
        for (int k = 0; k < 16; k++) {
            float4 a = *(const float4*)&As[buf][k][ty * 4];
            ulonglong2 b = *(const ulonglong2*)&Bs[buf][k][tx * 4];
            ull aa0 = pack2(a.x, a.x), aa1 = pack2(a.y, a.y);
            ull aa2 = pack2(a.z, a.z), aa3 = pack2(a.w, a.w);
            ffma2(c2[0][0], aa0, b.x); ffma2(c2[0][1], aa0, b.y);
            ffma2(c2[1][0], aa1, b.x); ffma2(c2[1][1], aa1, b.y);
            ffma2(c2[2][0], aa2, b.x); ffma2(c2[2][1], aa2, b.y);
            ffma2(c2[3][0], aa3, b.x); ffma2(c2[3][1], aa3, b.y);
        }
        if (ks < 31) {
            const int nb = buf ^ 1;
            As[nb][lk + 0][lr] = av.x; As[nb][lk + 1][lr] = av.y;
            As[nb][lk + 2][lr] = av.z; As[nb][lk + 3][lr] = av.w;
            Bs[nb][lk + 0][lr] = bw.x; Bs[nb][lk + 1][lr] = bw.y;
            Bs[nb][lk + 2][lr] = bw.z; Bs[nb][lk + 3][lr] = bw.w;
        }
    }

    const int nb = n0 + tx * 4;
    float4 bias4 = *(const float4*)&bv[nb];
#pragma unroll
    for (int i = 0; i < 4; i++) {
        float2 p0 = unpack2(c2[i][0]);
        float2 p1 = unpack2(c2[i][1]);
        float4 o;
        o.x = p0.x + bias4.x; o.y = p0.y + bias4.y;
        o.z = p1.x + bias4.z; o.w = p1.y + bias4.w;
        int m = m0 + ty * 4 + i;
        *(float4*)&outp[(size_t)m * G3H + nb] = o;
    }
}

// ------------------------------------------------------------------
// GRU gate combine (R9 verbatim)
// ------------------------------------------------------------------
__global__ void gru_combine_kernel(int cur) {
    int row = blockIdx.x;
    int col = threadIdx.x;
    int rp = g_perm[row];
    float hprev = g_h[cur][rp * Hd + col];
    size_t base = (size_t)row * G3H;
    float ir = g_gi[base + col];
    float iz = g_gi[base + Hd + col];
    float in_ = g_gi[base + 2 * Hd + col];
    float hr = g_gh[base + col];
    float hz = g_gh[base + Hd + col];
    float hn = g_gh[base + 2 * Hd + col];
    float r = 1.0f / (1.0f + expf(-(ir + hr)));
    float z = 1.0f / (1.0f + expf(-(iz + hz)));
    float n = tanhf(in_ + r * hn);
    float h = (1.0f - z) * n + z * hprev;
    g_h[1 - cur][row * Hd + col] = h;
    g_hT[col * BK + row] = h;
}

// ------------------------------------------------------------------
// Logits GEMM, M-split for occupancy: grid (250, 2), 128 threads,
// 64x128 tile per CTA, 4 CTAs/SM (16 warps). Every FFMA2 chain and the
// per-128-col-tile reduction tree are operand-identical to the frozen
// R13 kernel (M-tiling does not touch k-order or the shuffle tree),
// so logits / pmax / psum are bit-identical.
// ------------------------------------------------------------------
__global__ __launch_bounds__(128, 4) void logits_kernel(
    const float* __restrict__ W, const float* __restrict__ bias,
    float* __restrict__ out_logits)
{
    __shared__ __align__(16) float As[2][16][64];
    __shared__ __align__(16) float Bs[2][16][128];

    const int tid = threadIdx.x;
    const int bx  = blockIdx.x;
    const int m0  = blockIdx.y * 64;
    const int n0  = bx * 128;
    const int tx  = tid & 15, ty = tid >> 4;   // ty 0..7
    const float* hT = g_hT;

    ull c2[8][4];
#pragma unroll
    for (int i = 0; i < 8; i++)
#pragma unroll
        for (int j = 0; j < 4; j++) c2[i][j] = 0ULL;

    auto stage = [&](int ks, int buf) {
        const int k0 = ks * 16;
        // A: 16 x 64 floats = 256 cp16 -> 2 per thread
#pragma unroll
        for (int u = 0; u < 2; u++) {
            int f = tid + u * 128;
            int k = f >> 4;
            int c = (f & 15) << 2;
            cp16(&As[buf][k][c], hT + (size_t)(k0 + k) * BK + m0 + c);
        }
        // B: 16 x 128 floats = 512 cp16 -> 4 per thread
#pragma unroll
        for (int u = 0; u < 4; u++) {
            int f = tid + u * 128;
            int k = f >> 5;
            int c = (f & 31) << 2;
            cp16(&Bs[buf][k][c], W + (size_t)(k0 + k) * Vv + n0 + c);
        }
    };

    stage(0, 0);
    cp_commit();

#pragma unroll 1
    for (int ks = 0; ks < 32; ks++) {
        const int buf = ks & 1;
        if (ks < 31) stage(ks + 1, buf ^ 1);
        cp_commit();
        cp_wait1();
        __syncthreads();
#pragma unroll
        for (int k = 0; k < 16; k++) {
            float4 a0 = *(const float4*)&As[buf][k][ty * 8];
            float4 a1 = *(const float4*)&As[buf][k][ty * 8 + 4];
            ulonglong2 b01 = *(const ulonglong2*)&Bs[buf][k][tx * 8];
            ulonglong2 b23 = *(const ulonglong2*)&Bs[buf][k][tx * 8 + 4];
            ull b0 = b01.x, b1 = b01.y, b2 = b23.x, b3 = b23.y;
            ull aa[8];
            aa[0] = pack2(a0.x, a0.x); aa[1] = pack2(a0.y, a0.y);
            aa[2] = pack2(a0.z, a0.z); aa[3] = pack2(a0.w, a0.w);
            aa[4] = pack2(a1.x, a1.x); aa[5] = pack2(a1.y, a1.y);
            aa[6] = pack2(a1.z, a1.z); aa[7] = pack2(a1.w, a1.w);
#pragma unroll
            for (int i = 0; i < 8; i++) {
                ffma2(c2[i][0], aa[i], b0);
                ffma2(c2[i][1], aa[i], b1);
                ffma2(c2[i][2], aa[i], b2);
                ffma2(c2[i][3], aa[i], b3);
            }
        }
        __syncthreads();
    }

    // Epilogue (R5 reduction tree verbatim; rows offset by m0)
    const int col0 = n0 + tx * 8;
    float4 bb0 = *(const float4*)&bias[col0];
    float4 bb1 = *(const float4*)&bias[col0 + 4];
#pragma unroll
    for (int i = 0; i < 8; i++) {
        float2 p0 = unpack2(c2[i][0]);
        float2 p1 = unpack2(c2[i][1]);
        float2 p2 = unpack2(c2[i][2]);
        float2 p3 = unpack2(c2[i][3]);
        float v0 = p0.x + bb0.x, v1 = p0.y + bb0.y;
        float v2 = p1.x + bb0.z, v3 = p1.y + bb0.w;
        float v4 = p2.x + bb1.x, v5 = p2.y + bb1.y;
        float v6 = p3.x + bb1.z, v7 = p3.y + bb1.w;
        int row = m0 + ty * 8 + i;
        float4 w0 = make_float4(v0, v1, v2, v3);
        float4 w1 = make_float4(v4, v5, v6, v7);
        *(float4*)&out_logits[(size_t)row * Vv + col0]     = w0;
        *(float4*)&out_logits[(size_t)row * Vv + col0 + 4] = w1;

        float m = fmaxf(fmaxf(fmaxf(v0, v1), fmaxf(v2, v3)),
                        fmaxf(fmaxf(v4, v5), fmaxf(v6, v7)));
#pragma unroll
        for (int off = 8; off >= 1; off >>= 1)
            m = fmaxf(m, __shfl_xor_sync(0xffffffffu, m, off, 16));
        float s = __expf(v0 - m) + __expf(v1 - m) + __expf(v2 - m) + __expf(v3 - m)
                + __expf(v4 - m) + __expf(v5 - m) + __expf(v6 - m) + __expf(v7 - m);
#pragma unroll
        for (int off = 8; off >= 1; off >>= 1)
            s += __shfl_xor_sync(0xffffffffu, s, off, 16);
        if (tx == 0) {
            g_pmax[bx * BK + row] = m;
            g_psum[bx * BK + row] = s;
        }
    }
}

// ------------------------------------------------------------------
// Pass 2 + inline LSE (overlap) + fused final merge (R13 verbatim).
// grid (125, 16), 512 threads.
// ------------------------------------------------------------------
__global__ __launch_bounds__(512) void pass2_kernel(
    float* __restrict__ logits,
    float* out_scores, float* out_syms, float* out_preds, int t)
{
    const int bx = blockIdx.x;
    const int b  = blockIdx.y;
    const int tid  = threadIdx.x;
    const int w    = tid >> 5;     // 16 warps
    const int lane = tid & 31;
    const int r    = w & 7;        // beam
    const int half = w >> 3;       // col half
    const int row  = b * 8 + r;
    const int vcol = bx * 256 + half * 128 + lane * 4;

    // Prefetch logits BEFORE any lse wait (overlaps spin with memory)
    float4 v = *(float4*)&logits[(size_t)row * Vv + vcol];

    // --- inline LSE: 8 designated wave-1 blocks, verbatim R12 numerics ---
    __shared__ float spmax[NT * 16];
    __shared__ float spsum[NT * 16];

    if (b == 0 && bx < 8) {
        const int r0 = bx * 16;
        for (int idx = tid; idx < NT * 16; idx += 512) {
            int j = idx >> 4;
            int i = idx & 15;
            spmax[idx] = g_pmax[j * BK + r0 + i];
            spsum[idx] = g_psum[j * BK + r0 + i];
        }
        __syncthreads();
        if (tid < 16) {
            const int i = tid;
            float m = neg_inf();
#pragma unroll 5
            for (int j = 0; j < NT; j++) m = fmaxf(m, spmax[j * 16 + i]);
            float s = 0.0f;
#pragma unroll 5
            for (int j = 0; j < NT; j++)
                s += spsum[j * 16 + i] * __expf(spmax[j * 16 + i] - m);
            g_lse[r0 + i] = m + logf(s);
        }
        __threadfence();
        __syncthreads();
        if (tid == 0) atomicAdd(&g_lseCtr, 1);
    }

    // All blocks wait until all 8 lse slices for step t are published
    if (tid == 0) {
        const int target = (t + 1) * 8;
        while (atomicAdd(&g_lseCtr, 0) < target) __nanosleep(32);
    }
    __syncthreads();
    __threadfence();

    float lse = g_lse[row];
    float sc  = g_scores[row];

    v.x -= lse; v.y -= lse; v.z -= lse; v.w -= lse;
    *(float4*)&logits[(size_t)row * Vv + vcol] = v;

    ull key[4];
    key[0] = make_key(sc + v.x, (unsigned)(r * Vv + vcol + 0));
    key[1] = make_key(sc + v.y, (unsigned)(r * Vv + vcol + 1));
    key[2] = make_key(sc + v.z, (unsigned)(r * Vv + vcol + 2));
    key[3] = make_key(sc + v.w, (unsigned)(r * Vv + vcol + 3));

    __shared__ ull wtop[16 * 8];

    // per-warp top-8 (warp-local only, no block syncs)
#pragma unroll 1
    for (int round = 0; round < 8; round++) {
        ull loc = key[0];
        if (key[1] > loc) loc = key[1];
        if (key[2] > loc) loc = key[2];
        if (key[3] > loc) loc = key[3];
#pragma unroll
        for (int off = 16; off >= 1; off >>= 1) {
            ull o = __shfl_xor_sync(0xffffffffu, loc, off);
            if (o > loc) loc = o;
        }
        if (lane == 0) wtop[w * 8 + round] = loc;
#pragma unroll
        for (int j = 0; j < 4; j++) if (key[j] == loc) key[j] = 0ULL;
    }
    __syncthreads();

    // warp 0 merges the 128 survivors -> exact block top-8
    if (w == 0) {
        ull k4[4];
#pragma unroll
        for (int i = 0; i < 4; i++) k4[i] = wtop[lane * 4 + i];
#pragma unroll 1
        for (int round = 0; round < 8; round++) {
            ull loc = k4[0];
            if (k4[1] > loc) loc = k4[1];
            if (k4[2] > loc) loc = k4[2];
            if (k4[3] > loc) loc = k4[3];
#pragma unroll
            for (int off = 16; off >= 1; off >>= 1) {
                ull o = __shfl_xor_sync(0xffffffffu, loc, off);
                if (o > loc) loc = o;
            }
            if (lane == 0) g_ckey[((size_t)b * NT2 + bx) * 8 + round] = loc;
#pragma unroll
            for (int j = 0; j < 4; j++) if (k4[j] == loc) k4[j] = 0ULL;
        }
    }

    // Last-block fused merge
    __threadfence();
    __syncthreads();
    __shared__ int amLast;
    if (tid == 0) amLast = (atomicAdd(&g_ctrB, 1) == NT2 * Bb - 1);
    __syncthreads();
    if (!amLast) return;
    __threadfence();
    if (tid == 0) g_ctrB = 0;

    // warp w = batch w: top-8 of its 1000 candidates
    ull L[8];
#pragma unroll
    for (int i = 0; i < 8; i++) L[i] = 0ULL;
    const int base = w * (NT2 * 8);
    for (int j = lane; j < NT2 * 8; j += 32) {
        ull k = g_ckey[base + j];
        if (k > L[7]) {
            L[7] = k;
#pragma unroll
            for (int i = 7; i > 0; i--)
                if (L[i] > L[i - 1]) { ull tv = L[i - 1]; L[i - 1] = L[i]; L[i] = tv; }
        }
    }
    for (int k = 0; k < 8; k++) {
        ull mx = L[0];
#pragma unroll
        for (int off = 16; off >= 1; off >>= 1) {
            ull o = __shfl_xor_sync(0xffffffffu, mx, off);
            if (o > mx) mx = o;
        }
        if (L[0] == mx) {   // unique keys -> exactly one lane pops
            L[0] = L[1]; L[1] = L[2]; L[2] = L[3]; L[3] = L[4];
            L[4] = L[5]; L[5] = L[6]; L[6] = L[7]; L[7] = 0ULL;
        }
        if (lane == 0) {
            float val = key_val(mx);
            unsigned idx = key_idx(mx);
            int token = (int)(idx % (unsigned)Vv);
            int beam  = (int)(idx / (unsigned)Vv);
            int orow  = w * 8 + k;
            int pred  = w * 8 + beam;
            if (out_scores) {
                out_scores[orow] = val;           // pre-EOS-mask
                out_syms[orow]   = (float)token;
                out_preds[orow]  = (float)pred;
            }
            g_tokens[orow] = token;
            g_scores[orow] = (token == EOS_T) ? neg_inf() : val;
            g_perm[orow]   = pred;
        }
    }
}

// ------------------------------------------------------------------
__global__ void final_kernel(float* __restrict__ out_hidden) {
    int row = blockIdx.x;
    int c = threadIdx.x;
    out_hidden[row * Hd + c] = g_h[0][g_perm[row] * Hd + c];
}

// ------------------------------------------------------------------
extern "C" void kernel_launch(void* const* d_in, const int* in_sizes, int n_in,
                              void* d_out, int out_size) {
    const float* enc   = (const float*)d_in[0];
    const float* emb   = (const float*)d_in[1];
    const float* w_ih  = (const float*)d_in[2];
    const float* w_hh  = (const float*)d_in[3];
    const float* b_ih  = (const float*)d_in[4];
    const float* b_hh  = (const float*)d_in[5];
    const float* w_out = (const float*)d_in[6];
    const float* b_out = (const float*)d_in[7];

    float* out = (float*)d_out;
    const size_t outs_sz = (size_t)Tt * BK * Vv;
    const size_t total   = outs_sz + 3 * (size_t)Tt * BK + (size_t)BK * Hd;
    const bool has_tail  = ((size_t)(unsigned)out_size >= total);

    float* out_logp   = out;
    float* out_scores = has_tail ? out + outs_sz : nullptr;
    float* out_syms   = has_tail ? out_scores + Tt * BK : nullptr;
    float* out_preds  = has_tail ? out_syms + Tt * BK : nullptr;
    float* out_hidden = has_tail ? out_preds + Tt * BK : nullptr;

    init_kernel<<<BK, Hd>>>(enc);

    for (int t = 0; t < Tt; t++) {
        int cur = t & 1;
        gru_gemm_kernel<<<dim3(24, 2, 2), 256>>>(emb, w_ih, w_hh, b_ih, b_hh, cur);
        gru_combine_kernel<<<BK, Hd>>>(cur);

        float* logits_t = out_logp + (size_t)t * BK * Vv;
        logits_kernel<<<dim3(NT, 2), 128>>>(w_out, b_out, logits_t);
        pass2_kernel<<<dim3(NT2, Bb), 512>>>(
            logits_t,
            has_tail ? out_scores + (size_t)t * BK : nullptr,
            has_tail ? out_syms   + (size_t)t * BK : nullptr,
            has_tail ? out_preds  + (size_t)t * BK : nullptr,
            t);
    }

    if (has_tail) final_kernel<<<BK, Hd>>>(out_hidden);
}